// round 9
// baseline (speedup 1.0000x reference)
#include <cuda_runtime.h>
#include <cuda_bf16.h>
#include <math.h>
#include <stdint.h>

// ---------------- problem constants ----------------
#define BATCH 64
#define SEQ   64
#define EMB   256
#define UNITS 512
#define GRU   256
#define FC    1024
#define VOCAB 50000

// ---------------- scratch (device globals; no allocation allowed) ----------------
__device__ float g_hidproj[BATCH * UNITS];
__device__ float g_qp[BATCH * SEQ * UNITS];
__device__ float g_score[BATCH * SEQ];
__device__ float g_gx[BATCH * 2 * EMB];
__device__ float g_fcin[BATCH * (GRU + UNITS)];
__device__ float g_t1[BATCH * FC];
__device__ float g_t2[BATCH * FC];

// ---------------- tf32 helpers (sm_80+ baseline PTX; no 'a' features) ----------------
__device__ __forceinline__ uint32_t tf32rn(float x) {
    uint32_t u;
    asm("cvt.rn.tf32.f32 %0, %1;" : "=r"(u) : "f"(x));
    return u;
}
__device__ __forceinline__ void mma_m16n8k8(float* c, uint4 a, uint2 b) {
    asm volatile(
        "mma.sync.aligned.m16n8k8.row.col.f32.tf32.tf32.f32 "
        "{%0,%1,%2,%3}, {%4,%5,%6,%7}, {%8,%9}, {%0,%1,%2,%3};"
        : "+f"(c[0]), "+f"(c[1]), "+f"(c[2]), "+f"(c[3])
        : "r"(a.x), "r"(a.y), "r"(a.z), "r"(a.w), "r"(b.x), "r"(b.y));
}

// ================= tf32 mma.sync logits GEMM =================
// C[64, 50000] = t2[64,1024] @ Wo[1024,50000] + bo
// CTA tile 64x128, 8 warps (4M x 2N), warp tile 16x64, Kc=32, 32 stages,
// double-buffered fragment-ordered smem (conflict-free LDS.128 / LDS.64).
#define LM_NSTG 32

__global__ __launch_bounds__(256, 1) void logits_mma(
    const float* __restrict__ A,    // t2 [64,1024]
    const float* __restrict__ Bm,   // Wo [1024,50000]
    const float* __restrict__ bias, // bo [50000]
    float* __restrict__ C)
{
    __shared__ float Asf[2][2048];  // [mt4|ks4][lane32][reg4]
    __shared__ float Bsf[2][4096];  // [nt2|j8][ks4][lane32][reg2]

    const int tid = threadIdx.x, lane = tid & 31, wid = tid >> 5;
    const int n0 = blockIdx.x * 128;
    const int wm = wid & 3, wn = wid >> 2;

    // ---- A staging geometry: 2 float4 per thread per stage ----
    int am[2], ak4[2]; int asoff[2];
#pragma unroll
    for (int i = 0; i < 2; i++) {
        int idx = tid + i * 256;            // 0..511 float4 of 64x32 tile
        am[i] = idx >> 3; ak4[i] = idx & 7; // row m, k-quad
        int mt = am[i] >> 4, g = am[i] & 7, hm = (am[i] >> 3) & 1;
        int ks = ak4[i] >> 1, hk = ak4[i] & 1;
        asoff[i] = ((mt * 4 + ks) * 32 + g * 4) * 4 + hm + 2 * hk;  // +4 per c
    }
    // ---- B staging geometry: 4 float4 per thread per stage ----
    const int bn4 = tid & 31;                       // float4 column index (fixed)
    const bool bvalid = (n0 + bn4 * 4) < VOCAB;
    int bk[4]; int bsoff[4];
#pragma unroll
    for (int i = 0; i < 4; i++) {
        int k = (tid >> 5) + i * 8;                 // k row within 32
        bk[i] = k;
        int nt = bn4 >> 4, j = (bn4 & 15) >> 1, gb = (bn4 & 1) * 4;
        int t = k & 3, hk = (k >> 2) & 1, ks = k >> 3;
        bsoff[i] = (((nt * 8 + j) * 4 + ks) * 32 + gb * 4 + t) * 2 + hk;  // +8 per c
    }

    float acc[8][4];
#pragma unroll
    for (int j = 0; j < 8; j++)
#pragma unroll
        for (int q = 0; q < 4; q++) acc[j][q] = 0.f;

    float4 ar[2], br[4];

    // ---- prefetch + stage 0 ----
#pragma unroll
    for (int i = 0; i < 2; i++)
        ar[i] = *(const float4*)&A[am[i] * 1024 + ak4[i] * 4];
#pragma unroll
    for (int i = 0; i < 4; i++)
        br[i] = bvalid ? *(const float4*)&Bm[bk[i] * VOCAB + n0 + bn4 * 4]
                       : make_float4(0.f, 0.f, 0.f, 0.f);
#pragma unroll
    for (int i = 0; i < 2; i++) {
        const float* v = (const float*)&ar[i];
#pragma unroll
        for (int c = 0; c < 4; c++)
            Asf[0][asoff[i] + c * 4] = __uint_as_float(tf32rn(v[c]));
    }
#pragma unroll
    for (int i = 0; i < 4; i++) {
        const float* v = (const float*)&br[i];
#pragma unroll
        for (int c = 0; c < 4; c++)
            Bsf[0][bsoff[i] + c * 8] = __uint_as_float(tf32rn(v[c]));
    }
    __syncthreads();

    for (int s = 0; s < LM_NSTG; s++) {
        const int b = s & 1;
        if (s + 1 < LM_NSTG) {
            const int kbase = (s + 1) * 32;
#pragma unroll
            for (int i = 0; i < 2; i++)
                ar[i] = *(const float4*)&A[am[i] * 1024 + kbase + ak4[i] * 4];
#pragma unroll
            for (int i = 0; i < 4; i++)
                br[i] = bvalid ? *(const float4*)&Bm[(kbase + bk[i]) * VOCAB + n0 + bn4 * 4]
                               : make_float4(0.f, 0.f, 0.f, 0.f);
        }
        // ---- compute on buffer b ----
#pragma unroll
        for (int ks = 0; ks < 4; ks++) {
            uint4 av = *(const uint4*)&Asf[b][(wm * 4 + ks) * 128 + lane * 4];
#pragma unroll
            for (int j = 0; j < 8; j++) {
                uint2 bv = *(const uint2*)&Bsf[b][(wn * 8 + j) * 256 + ks * 64 + lane * 2];
                mma_m16n8k8(acc[j], av, bv);
            }
        }
        if (s + 1 < LM_NSTG) {
            const int nb = b ^ 1;
#pragma unroll
            for (int i = 0; i < 2; i++) {
                const float* v = (const float*)&ar[i];
#pragma unroll
                for (int c = 0; c < 4; c++)
                    Asf[nb][asoff[i] + c * 4] = __uint_as_float(tf32rn(v[c]));
            }
#pragma unroll
            for (int i = 0; i < 4; i++) {
                const float* v = (const float*)&br[i];
#pragma unroll
                for (int c = 0; c < 4; c++)
                    Bsf[nb][bsoff[i] + c * 8] = __uint_as_float(tf32rn(v[c]));
            }
        }
        __syncthreads();
    }

    // ---- epilogue: direct STG.64 per fragment ----
    const int g = lane >> 2, t = lane & 3;
    const int r0 = wm * 16 + g, r1 = r0 + 8;
#pragma unroll
    for (int j = 0; j < 8; j++) {
        int col = n0 + wn * 64 + j * 8 + t * 2;
        if (col < VOCAB) {
            float2 bo2 = make_float2(bias[col], bias[col + 1]);
            float2 o0 = make_float2(acc[j][0] + bo2.x, acc[j][1] + bo2.y);
            float2 o1 = make_float2(acc[j][2] + bo2.x, acc[j][3] + bo2.y);
            *(float2*)&C[r0 * VOCAB + col] = o0;
            *(float2*)&C[r1 * VOCAB + col] = o1;
        }
    }
}

// ---------------- fp32 tiled GEMM (qs@W1) ----------------
__global__ __launch_bounds__(256) void gemm64x128(
    const float* __restrict__ A, const float* __restrict__ B,
    const float* __restrict__ bias, float* __restrict__ C,
    int M, int N, int K)
{
    __shared__ float  As[32][65];
    __shared__ float4 Bs[32][32];
    const int tid = threadIdx.x;
    const int tx = tid & 31, ty = tid >> 5;
    const int n0 = blockIdx.x * 128, m0 = blockIdx.y * 64;
    float acc[8][4];
#pragma unroll
    for (int i = 0; i < 8; i++)
#pragma unroll
        for (int j = 0; j < 4; j++) acc[i][j] = 0.f;
    for (int k0 = 0; k0 < K; k0 += 32) {
#pragma unroll
        for (int e = 0; e < 8; e++) {
            int idx = tid + e * 256;
            int k = idx & 31, m = idx >> 5;
            As[k][m] = A[(m0 + m) * K + (k0 + k)];
        }
#pragma unroll
        for (int e = 0; e < 4; e++) {
            int idx = tid + e * 256;
            int k = idx >> 5, n4 = idx & 31;
            int n = n0 + n4 * 4;
            float4 v = make_float4(0.f, 0.f, 0.f, 0.f);
            if (n + 3 < N) v = *(const float4*)&B[(k0 + k) * N + n];
            Bs[k][n4] = v;
        }
        __syncthreads();
#pragma unroll
        for (int kk = 0; kk < 32; kk++) {
            float4 b = Bs[kk][tx];
            float a[8];
#pragma unroll
            for (int i = 0; i < 8; i++) a[i] = As[kk][ty + 8 * i];
#pragma unroll
            for (int i = 0; i < 8; i++) {
                acc[i][0] = fmaf(a[i], b.x, acc[i][0]);
                acc[i][1] = fmaf(a[i], b.y, acc[i][1]);
                acc[i][2] = fmaf(a[i], b.z, acc[i][2]);
                acc[i][3] = fmaf(a[i], b.w, acc[i][3]);
            }
        }
        __syncthreads();
    }
    const int nbase = n0 + tx * 4;
#pragma unroll
    for (int i = 0; i < 8; i++) {
        int m = m0 + ty + 8 * i;
#pragma unroll
        for (int j = 0; j < 4; j++) {
            int n = nbase + j;
            if (n < N) C[m * N + n] = acc[i][j] + (bias ? bias[n] : 0.f);
        }
    }
}

// ---------------- hidden @ W2 + b2 ----------------
__global__ __launch_bounds__(512) void hidproj_k(
    const float* __restrict__ hidden, const float* __restrict__ W2,
    const float* __restrict__ b2, float* __restrict__ out)
{
    __shared__ float sh[UNITS];
    int b = blockIdx.x, t = threadIdx.x;
    sh[t] = hidden[b * UNITS + t];
    __syncthreads();
    float acc = b2[t];
#pragma unroll 8
    for (int k = 0; k < UNITS; k++) acc = fmaf(sh[k], W2[k * UNITS + t], acc);
    out[b * UNITS + t] = acc;
}

// ---------------- attention score ----------------
__global__ __launch_bounds__(256) void score_k(
    const float* __restrict__ qp, const float* __restrict__ hidproj,
    const float* __restrict__ V, const float* __restrict__ bV,
    float* __restrict__ score)
{
    int bs = blockIdx.x, b = bs >> 6, t = threadIdx.x;
    const float* qrow = qp + bs * UNITS;
    const float* hp = hidproj + b * UNITS;
    float s = 0.f;
    for (int u = t; u < UNITS; u += 256)
        s += tanhf(qrow[u] + hp[u]) * V[u];
    __shared__ float red[256];
    red[t] = s; __syncthreads();
    for (int o = 128; o > 0; o >>= 1) {
        if (t < o) red[t] += red[t + o];
        __syncthreads();
    }
    if (t == 0) score[bs] = red[0] + bV[0];
}

// ---------------- softmax + context + embedding (grid: 4 x B, 64 thr) ----------------
__global__ __launch_bounds__(64) void softctx_k(
    const float* __restrict__ score, const float* __restrict__ qs,
    const int* __restrict__ x, const float* __restrict__ E,
    float* __restrict__ weights_out, float* __restrict__ gx)
{
    int b = blockIdx.y, part = blockIdx.x, t = threadIdx.x;
    __shared__ float w[SEQ];
    w[t] = score[b * SEQ + t];
    __syncthreads();
    if (t < 32) {
        float a0 = w[t], a1 = w[t + 32];
        float m = fmaxf(a0, a1);
#pragma unroll
        for (int o = 16; o; o >>= 1) m = fmaxf(m, __shfl_xor_sync(0xffffffff, m, o));
        float e0 = expf(a0 - m), e1 = expf(a1 - m);
        float s = e0 + e1;
#pragma unroll
        for (int o = 16; o; o >>= 1) s += __shfl_xor_sync(0xffffffff, s, o);
        float inv = 1.f / s;
        w[t] = e0 * inv; w[t + 32] = e1 * inv;
    }
    __syncthreads();
    if (part == 0) weights_out[b * SEQ + t] = w[t];
    int e = part * 64 + t;
    float c = 0.f;
#pragma unroll 8
    for (int s2 = 0; s2 < SEQ; s2++)
        c = fmaf(w[s2], qs[(b * SEQ + s2) * EMB + e], c);
    gx[b * 2 * EMB + EMB + e] = c;
    gx[b * 2 * EMB + e] = E[x[b] * EMB + e];
}

// ---------------- GRU step (h0 = 0) ----------------
__global__ __launch_bounds__(256) void gru_k(
    const float* __restrict__ gx, const float* __restrict__ Kg,
    const float* __restrict__ bg, const float* __restrict__ features,
    float* __restrict__ state_out, float* __restrict__ fc_in)
{
    int b = blockIdx.x, g = threadIdx.x;
    __shared__ float sh[2 * EMB];
    sh[g] = gx[b * 2 * EMB + g];
    sh[g + 256] = gx[b * 2 * EMB + 256 + g];
    __syncthreads();
    float mz = bg[g], mr = bg[GRU + g], mh = bg[2 * GRU + g];
#pragma unroll 4
    for (int k = 0; k < 2 * EMB; k++) {
        float a = sh[k];
        const float* kr = Kg + k * 3 * GRU;
        mz = fmaf(a, kr[g], mz);
        mr = fmaf(a, kr[GRU + g], mr);
        mh = fmaf(a, kr[2 * GRU + g], mh);
    }
    const float* bgh = bg + 3 * GRU;
    float z = 1.f / (1.f + expf(-(mz + bgh[g])));
    float r = 1.f / (1.f + expf(-(mr + bgh[GRU + g])));
    float hc = tanhf(mh + r * bgh[2 * GRU + g]);
    float st = (1.f - z) * hc;
    state_out[b * GRU + g] = st;
    fc_in[b * (GRU + UNITS) + g] = st;
    fc_in[b * (GRU + UNITS) + GRU + g] = features[b * UNITS + g];
    fc_in[b * (GRU + UNITS) + GRU + 256 + g] = features[b * UNITS + 256 + g];
}

// ---------------- naive dense ----------------
__global__ void dense_k(const float* __restrict__ in, const float* __restrict__ W,
                        const float* __restrict__ bias, float* __restrict__ out,
                        int IN, int OUT)
{
    extern __shared__ float sh[];
    int b = blockIdx.y;
    int o = blockIdx.x * blockDim.x + threadIdx.x;
    for (int k = threadIdx.x; k < IN; k += blockDim.x) sh[k] = in[b * IN + k];
    __syncthreads();
    float acc = bias[o];
#pragma unroll 8
    for (int k = 0; k < IN; k++) acc = fmaf(sh[k], W[k * OUT + o], acc);
    out[b * OUT + o] = acc;
}

// ---------------- launch ----------------
extern "C" void kernel_launch(void* const* d_in, const int* in_sizes, int n_in,
                              void* d_out, int out_size)
{
    const int*   x        = (const int*)  d_in[0];
    const float* qs       = (const float*)d_in[1];
    const float* features = (const float*)d_in[2];
    const float* hidden   = (const float*)d_in[3];
    const float* E        = (const float*)d_in[4];
    const float* W1       = (const float*)d_in[5];
    const float* b1       = (const float*)d_in[6];
    const float* W2       = (const float*)d_in[7];
    const float* b2       = (const float*)d_in[8];
    const float* V        = (const float*)d_in[9];
    const float* bV       = (const float*)d_in[10];
    const float* Kg       = (const float*)d_in[11];
    /* d_in[12] = Ug dead (h0 == 0) */
    const float* bg       = (const float*)d_in[13];
    const float* Wf1      = (const float*)d_in[14];
    const float* bf1      = (const float*)d_in[15];
    const float* Wf2      = (const float*)d_in[16];
    const float* bf2      = (const float*)d_in[17];
    const float* Wo       = (const float*)d_in[18];
    const float* bo       = (const float*)d_in[19];

    float* out = (float*)d_out;
    float* logits      = out;
    float* state_out   = out + BATCH * VOCAB;
    float* weights_out = state_out + BATCH * GRU;

    float *qp, *hidproj, *score, *gx, *fcin, *t1, *t2;
    cudaGetSymbolAddress((void**)&qp,      g_qp);
    cudaGetSymbolAddress((void**)&hidproj, g_hidproj);
    cudaGetSymbolAddress((void**)&score,   g_score);
    cudaGetSymbolAddress((void**)&gx,      g_gx);
    cudaGetSymbolAddress((void**)&fcin,    g_fcin);
    cudaGetSymbolAddress((void**)&t1,      g_t1);
    cudaGetSymbolAddress((void**)&t2,      g_t2);

    hidproj_k<<<BATCH, UNITS>>>(hidden, W2, b2, hidproj);
    gemm64x128<<<dim3(UNITS / 128, (BATCH * SEQ) / 64), 256>>>(
        qs, W1, b1, qp, BATCH * SEQ, UNITS, EMB);
    score_k<<<BATCH * SEQ, 256>>>(qp, hidproj, V, bV, score);
    softctx_k<<<dim3(4, BATCH), 64>>>(score, qs, x, E, weights_out, gx);
    gru_k<<<BATCH, 256>>>(gx, Kg, bg, features, state_out, fcin);
    dense_k<<<dim3(FC / 256, BATCH), 256, (GRU + UNITS) * sizeof(float)>>>(
        fcin, Wf1, bf1, t1, GRU + UNITS, FC);
    dense_k<<<dim3(FC / 256, BATCH), 256, FC * sizeof(float)>>>(
        t1, Wf2, bf2, t2, FC, FC);
    // tensor-core (mma.sync tf32) logits GEMM: 391 CTAs x 128-col tiles
    logits_mma<<<(VOCAB + 127) / 128, 256>>>(t2, Wo, bo, logits);
}

// round 10
// speedup vs baseline: 1.1748x; 1.1748x over previous
#include <cuda_runtime.h>
#include <cuda_bf16.h>
#include <math.h>
#include <stdint.h>

// ---------------- problem constants ----------------
#define BATCH 64
#define SEQ   64
#define EMB   256
#define UNITS 512
#define GRU   256
#define FC    1024
#define VOCAB 50000

// ---------------- scratch (device globals; no allocation allowed) ----------------
__device__ float g_hidproj[BATCH * UNITS];
__device__ float g_qp[BATCH * SEQ * UNITS];
__device__ float g_score[BATCH * SEQ];
__device__ float g_gx[BATCH * 2 * EMB];
__device__ float g_fcin[BATCH * (GRU + UNITS)];
__device__ float g_t1[BATCH * FC];
__device__ float g_t2[BATCH * FC];

// ---------------- packed dual-fp32 FMA (B300 FFMA2; baseline Blackwell PTX) ----------------
__device__ __forceinline__ uint64_t ffma2(uint64_t a, uint64_t b, uint64_t c) {
    uint64_t d;
    asm("fma.rn.f32x2 %0, %1, %2, %3;" : "=l"(d) : "l"(a), "l"(b), "l"(c));
    return d;
}

// ================= f32x2 SIMT GEMM =================
// C[M,N] = A[M,K] @ B[K,N] + bias.  CTA tile 64x128, 256 threads.
// Thread tile 8(m) x 4(n); accumulators are f32x2 pairs along N.
// A is staged DUPLICATED in smem (Asd[k][2m]=Asd[k][2m+1]=A[m,k]) so the
// a-operand of each FFMA2 is a single broadcast LDS.64 — no packing movs.
// B pairs come straight from LDS.64 of the normal row-major Bs tile.
// Double-buffered; per-kk per-warp: 8 LDS.64(bc) + 2 LDS.64 + 16 FFMA2.
// Requires: M % 64 == 0, K % 32 == 0, N % 4 == 0.
#define GF_ROW 130                       // Asd row stride in floats (8B-aligned, low conflict)
#define GF_ASZ (32 * GF_ROW)
#define GF_BSZ (32 * 128)
#define GF_SMEM ((2 * GF_ASZ + 2 * GF_BSZ) * 4)   // 66048 bytes

__global__ __launch_bounds__(256) void gemm_f32x2(
    const float* __restrict__ A, const float* __restrict__ B,
    const float* __restrict__ bias, float* __restrict__ C,
    int M, int N, int K)
{
    extern __shared__ float sm[];
    float* Asd = sm;                     // [2][32][GF_ROW]
    float* Bs  = sm + 2 * GF_ASZ;        // [2][32][128]

    const int tid = threadIdx.x, tx = tid & 31, ty = tid >> 5;
    const int n0 = blockIdx.x * 128, m0 = blockIdx.y * 64;
    const int NT = K >> 5;

    uint64_t acc[8][2];
#pragma unroll
    for (int i = 0; i < 8; i++) { acc[i][0] = 0ull; acc[i][1] = 0ull; }

    const int bn = n0 + tx * 4;
    const bool bok = bn < N;             // N % 4 == 0 -> whole quad valid
    const int bkr = tid >> 5;            // B stage k-row base (0..7)

    float ar[8]; float4 br[4];

    // ---- prefetch + stage tile 0 into buffer 0 ----
#pragma unroll
    for (int e = 0; e < 8; e++) {
        int idx = tid + e * 256;         // k = idx&31 (lane-varying: coalesced), m = idx>>5
        ar[e] = A[(m0 + (idx >> 5)) * K + (idx & 31)];
    }
#pragma unroll
    for (int e = 0; e < 4; e++)
        br[e] = bok ? *(const float4*)&B[(bkr + e * 8) * N + bn]
                    : make_float4(0.f, 0.f, 0.f, 0.f);
#pragma unroll
    for (int e = 0; e < 8; e++) {
        int idx = tid + e * 256;
        *(float2*)&Asd[(idx & 31) * GF_ROW + 2 * (idx >> 5)] = make_float2(ar[e], ar[e]);
    }
#pragma unroll
    for (int e = 0; e < 4; e++)
        *(float4*)&Bs[(bkr + e * 8) * 128 + tx * 4] = br[e];
    __syncthreads();

    for (int s = 0; s < NT; s++) {
        const int b = s & 1;
        if (s + 1 < NT) {                // prefetch next tile into registers
            const int kb = (s + 1) << 5;
#pragma unroll
            for (int e = 0; e < 8; e++) {
                int idx = tid + e * 256;
                ar[e] = A[(m0 + (idx >> 5)) * K + kb + (idx & 31)];
            }
#pragma unroll
            for (int e = 0; e < 4; e++)
                br[e] = bok ? *(const float4*)&B[(kb + bkr + e * 8) * N + bn]
                            : make_float4(0.f, 0.f, 0.f, 0.f);
        }
        // ---- compute on buffer b ----
        const float* Ab = Asd + b * GF_ASZ + 2 * ty;
        const float* Bb = Bs  + b * GF_BSZ + tx * 4;
#pragma unroll 8
        for (int kk = 0; kk < 32; kk++) {
            uint64_t bb0 = *(const uint64_t*)(Bb + kk * 128);
            uint64_t bb1 = *(const uint64_t*)(Bb + kk * 128 + 2);
            const float* arow = Ab + kk * GF_ROW;
#pragma unroll
            for (int i = 0; i < 8; i++) {
                uint64_t aa = *(const uint64_t*)(arow + 16 * i);   // m = ty + 8*i, duplicated
                acc[i][0] = ffma2(aa, bb0, acc[i][0]);
                acc[i][1] = ffma2(aa, bb1, acc[i][1]);
            }
        }
        // ---- stage next tile into the other buffer ----
        if (s + 1 < NT) {
            const int nb = b ^ 1;
#pragma unroll
            for (int e = 0; e < 8; e++) {
                int idx = tid + e * 256;
                *(float2*)&Asd[nb * GF_ASZ + (idx & 31) * GF_ROW + 2 * (idx >> 5)] =
                    make_float2(ar[e], ar[e]);
            }
#pragma unroll
            for (int e = 0; e < 4; e++)
                *(float4*)&Bs[nb * GF_BSZ + (bkr + e * 8) * 128 + tx * 4] = br[e];
        }
        __syncthreads();
    }

    // ---- epilogue: coalesced STG.128 per row ----
    if (bok) {
        float4 bv = *(const float4*)&bias[bn];
#pragma unroll
        for (int i = 0; i < 8; i++) {
            int m = m0 + ty + 8 * i;
            float2 p0 = *(float2*)&acc[i][0];
            float2 p1 = *(float2*)&acc[i][1];
            float4 o = make_float4(p0.x + bv.x, p0.y + bv.y, p1.x + bv.z, p1.y + bv.w);
            *(float4*)&C[m * N + bn] = o;
        }
    }
}

// ---------------- hidden @ W2 + b2 ----------------
__global__ __launch_bounds__(512) void hidproj_k(
    const float* __restrict__ hidden, const float* __restrict__ W2,
    const float* __restrict__ b2, float* __restrict__ out)
{
    __shared__ float sh[UNITS];
    int b = blockIdx.x, t = threadIdx.x;
    sh[t] = hidden[b * UNITS + t];
    __syncthreads();
    float acc = b2[t];
#pragma unroll 8
    for (int k = 0; k < UNITS; k++) acc = fmaf(sh[k], W2[k * UNITS + t], acc);
    out[b * UNITS + t] = acc;
}

// ---------------- attention score ----------------
__global__ __launch_bounds__(256) void score_k(
    const float* __restrict__ qp, const float* __restrict__ hidproj,
    const float* __restrict__ V, const float* __restrict__ bV,
    float* __restrict__ score)
{
    int bs = blockIdx.x, b = bs >> 6, t = threadIdx.x;
    const float* qrow = qp + bs * UNITS;
    const float* hp = hidproj + b * UNITS;
    float s = 0.f;
    for (int u = t; u < UNITS; u += 256)
        s += tanhf(qrow[u] + hp[u]) * V[u];
    __shared__ float red[256];
    red[t] = s; __syncthreads();
    for (int o = 128; o > 0; o >>= 1) {
        if (t < o) red[t] += red[t + o];
        __syncthreads();
    }
    if (t == 0) score[bs] = red[0] + bV[0];
}

// ---------------- softmax + context + embedding (grid: 4 x B, 64 thr) ----------------
__global__ __launch_bounds__(64) void softctx_k(
    const float* __restrict__ score, const float* __restrict__ qs,
    const int* __restrict__ x, const float* __restrict__ E,
    float* __restrict__ weights_out, float* __restrict__ gx)
{
    int b = blockIdx.y, part = blockIdx.x, t = threadIdx.x;
    __shared__ float w[SEQ];
    w[t] = score[b * SEQ + t];
    __syncthreads();
    if (t < 32) {
        float a0 = w[t], a1 = w[t + 32];
        float m = fmaxf(a0, a1);
#pragma unroll
        for (int o = 16; o; o >>= 1) m = fmaxf(m, __shfl_xor_sync(0xffffffff, m, o));
        float e0 = expf(a0 - m), e1 = expf(a1 - m);
        float s = e0 + e1;
#pragma unroll
        for (int o = 16; o; o >>= 1) s += __shfl_xor_sync(0xffffffff, s, o);
        float inv = 1.f / s;
        w[t] = e0 * inv; w[t + 32] = e1 * inv;
    }
    __syncthreads();
    if (part == 0) weights_out[b * SEQ + t] = w[t];
    int e = part * 64 + t;
    float c = 0.f;
#pragma unroll 8
    for (int s2 = 0; s2 < SEQ; s2++)
        c = fmaf(w[s2], qs[(b * SEQ + s2) * EMB + e], c);
    gx[b * 2 * EMB + EMB + e] = c;
    gx[b * 2 * EMB + e] = E[x[b] * EMB + e];
}

// ---------------- GRU step (h0 = 0) ----------------
__global__ __launch_bounds__(256) void gru_k(
    const float* __restrict__ gx, const float* __restrict__ Kg,
    const float* __restrict__ bg, const float* __restrict__ features,
    float* __restrict__ state_out, float* __restrict__ fc_in)
{
    int b = blockIdx.x, g = threadIdx.x;
    __shared__ float sh[2 * EMB];
    sh[g] = gx[b * 2 * EMB + g];
    sh[g + 256] = gx[b * 2 * EMB + 256 + g];
    __syncthreads();
    float mz = bg[g], mr = bg[GRU + g], mh = bg[2 * GRU + g];
#pragma unroll 4
    for (int k = 0; k < 2 * EMB; k++) {
        float a = sh[k];
        const float* kr = Kg + k * 3 * GRU;
        mz = fmaf(a, kr[g], mz);
        mr = fmaf(a, kr[GRU + g], mr);
        mh = fmaf(a, kr[2 * GRU + g], mh);
    }
    const float* bgh = bg + 3 * GRU;
    float z = 1.f / (1.f + expf(-(mz + bgh[g])));
    float r = 1.f / (1.f + expf(-(mr + bgh[GRU + g])));
    float hc = tanhf(mh + r * bgh[2 * GRU + g]);
    float st = (1.f - z) * hc;
    state_out[b * GRU + g] = st;
    fc_in[b * (GRU + UNITS) + g] = st;
    fc_in[b * (GRU + UNITS) + GRU + g] = features[b * UNITS + g];
    fc_in[b * (GRU + UNITS) + GRU + 256 + g] = features[b * UNITS + 256 + g];
}

// ---------------- naive dense (fc1 / fc2) ----------------
__global__ void dense_k(const float* __restrict__ in, const float* __restrict__ W,
                        const float* __restrict__ bias, float* __restrict__ out,
                        int IN, int OUT)
{
    extern __shared__ float sh[];
    int b = blockIdx.y;
    int o = blockIdx.x * blockDim.x + threadIdx.x;
    for (int k = threadIdx.x; k < IN; k += blockDim.x) sh[k] = in[b * IN + k];
    __syncthreads();
    float acc = bias[o];
#pragma unroll 8
    for (int k = 0; k < IN; k++) acc = fmaf(sh[k], W[k * OUT + o], acc);
    out[b * OUT + o] = acc;
}

// ---------------- launch ----------------
extern "C" void kernel_launch(void* const* d_in, const int* in_sizes, int n_in,
                              void* d_out, int out_size)
{
    const int*   x        = (const int*)  d_in[0];
    const float* qs       = (const float*)d_in[1];
    const float* features = (const float*)d_in[2];
    const float* hidden   = (const float*)d_in[3];
    const float* E        = (const float*)d_in[4];
    const float* W1       = (const float*)d_in[5];
    const float* b1       = (const float*)d_in[6];
    const float* W2       = (const float*)d_in[7];
    const float* b2       = (const float*)d_in[8];
    const float* V        = (const float*)d_in[9];
    const float* bV       = (const float*)d_in[10];
    const float* Kg       = (const float*)d_in[11];
    /* d_in[12] = Ug dead (h0 == 0) */
    const float* bg       = (const float*)d_in[13];
    const float* Wf1      = (const float*)d_in[14];
    const float* bf1      = (const float*)d_in[15];
    const float* Wf2      = (const float*)d_in[16];
    const float* bf2      = (const float*)d_in[17];
    const float* Wo       = (const float*)d_in[18];
    const float* bo       = (const float*)d_in[19];

    float* out = (float*)d_out;
    float* logits      = out;
    float* state_out   = out + BATCH * VOCAB;
    float* weights_out = state_out + BATCH * GRU;

    float *qp, *hidproj, *score, *gx, *fcin, *t1, *t2;
    cudaGetSymbolAddress((void**)&qp,      g_qp);
    cudaGetSymbolAddress((void**)&hidproj, g_hidproj);
    cudaGetSymbolAddress((void**)&score,   g_score);
    cudaGetSymbolAddress((void**)&gx,      g_gx);
    cudaGetSymbolAddress((void**)&fcin,    g_fcin);
    cudaGetSymbolAddress((void**)&t1,      g_t1);
    cudaGetSymbolAddress((void**)&t2,      g_t2);

    cudaFuncSetAttribute(gemm_f32x2, cudaFuncAttributeMaxDynamicSharedMemorySize, GF_SMEM);

    hidproj_k<<<BATCH, UNITS>>>(hidden, W2, b2, hidproj);
    // qs @ W1 + b1 : M=4096, N=512, K=256
    gemm_f32x2<<<dim3(UNITS / 128, (BATCH * SEQ) / 64), 256, GF_SMEM>>>(
        qs, W1, b1, qp, BATCH * SEQ, UNITS, EMB);
    score_k<<<BATCH * SEQ, 256>>>(qp, hidproj, V, bV, score);
    softctx_k<<<dim3(4, BATCH), 64>>>(score, qs, x, E, weights_out, gx);
    gru_k<<<BATCH, 256>>>(gx, Kg, bg, features, state_out, fcin);
    dense_k<<<dim3(FC / 256, BATCH), 256, (GRU + UNITS) * sizeof(float)>>>(
        fcin, Wf1, bf1, t1, GRU + UNITS, FC);
    dense_k<<<dim3(FC / 256, BATCH), 256, FC * sizeof(float)>>>(
        t1, Wf2, bf2, t2, FC, FC);
    // logits: M=64, N=50000, K=1024 — FFMA2 path, 391 CTAs (one full wave)
    gemm_f32x2<<<dim3((VOCAB + 127) / 128, 1), 256, GF_SMEM>>>(
        t2, Wo, bo, logits, BATCH, VOCAB, FC);
}